// round 6
// baseline (speedup 1.0000x reference)
#include <cuda_runtime.h>
#include <math.h>

// Problem constants
#define Bc   8
#define Lc   2048
#define Dc   300
#define Hc   150
#define BLc  (Bc * Lc)   // 16384

// ---------------------------------------------------------------------------
// Device scratch (static globals — allocation-free per harness rules)
// ---------------------------------------------------------------------------
__device__ float g_Qh[BLc * Hc];                 // 9.8 MB  gated Q
__device__ float g_Ah[BLc * Hc];                 // 9.8 MB  gated A
__device__ float g_P [BLc * Hc];                 // 9.8 MB  Qh @ Wg + bg
__device__ float g_G [(size_t)Bc * Lc * Lc];     // 134 MB  scores, layout [b][a][q]
__device__ float g_Hm[BLc * Hc];                 // 9.8 MB  attention output

// ---------------------------------------------------------------------------
// Kernel 1: gated projection  Y = sigmoid(X@Wi+bi) * tanh(X@Wu+bu)
// X: [BLc, Dc], Wi/Wu: [Dc, Hc], Y: [BLc, Hc]
// Tile: 64 rows x 150 cols, KT=16. 256 threads, each 4 rows x 10 cols x 2 weights.
// ---------------------------------------------------------------------------
__global__ __launch_bounds__(256) void gate_kernel(
    const float* __restrict__ X,
    const float* __restrict__ Wi, const float* __restrict__ Wu,
    const float* __restrict__ bi, const float* __restrict__ bu,
    float* __restrict__ Y)
{
    __shared__ float Xs [64 * 17];
    __shared__ float Wis[16 * 160];
    __shared__ float Wus[16 * 160];

    const int tid = threadIdx.x;
    const int tx  = tid & 15;
    const int ty  = tid >> 4;
    const int rb  = blockIdx.x * 64;

    float accI[4][10];
    float accU[4][10];
    #pragma unroll
    for (int i = 0; i < 4; ++i)
        #pragma unroll
        for (int j = 0; j < 10; ++j) { accI[i][j] = 0.f; accU[i][j] = 0.f; }

    for (int kk = 0; kk < Dc; kk += 16) {
        // Load X tile [64][16] (row-major in smem, pad 17)
        #pragma unroll
        for (int r = 0; r < 4; ++r) {
            int idx = tid + 256 * r;
            int m = idx >> 4, k = idx & 15;
            float v = (kk + k < Dc) ? X[(size_t)(rb + m) * Dc + kk + k] : 0.f;
            Xs[m * 17 + k] = v;
        }
        // Load weight tiles [16][160], cols >= Hc zero-padded
        #pragma unroll
        for (int r = 0; r < 10; ++r) {
            int idx = tid + 256 * r;
            int k = idx / 160, c = idx - k * 160;
            bool ok = (c < Hc) && (kk + k < Dc);
            Wis[k * 160 + c] = ok ? Wi[(size_t)(kk + k) * Hc + c] : 0.f;
            Wus[k * 160 + c] = ok ? Wu[(size_t)(kk + k) * Hc + c] : 0.f;
        }
        __syncthreads();

        #pragma unroll
        for (int k = 0; k < 16; ++k) {
            float xv[4];
            #pragma unroll
            for (int i = 0; i < 4; ++i) xv[i] = Xs[(ty * 4 + i) * 17 + k];
            #pragma unroll
            for (int j = 0; j < 10; ++j) {
                float wi = Wis[k * 160 + tx + 16 * j];
                float wu = Wus[k * 160 + tx + 16 * j];
                #pragma unroll
                for (int i = 0; i < 4; ++i) {
                    accI[i][j] += xv[i] * wi;
                    accU[i][j] += xv[i] * wu;
                }
            }
        }
        __syncthreads();
    }

    #pragma unroll
    for (int j = 0; j < 10; ++j) {
        int c = tx + 16 * j;
        if (c < Hc) {
            float bI = bi[c], bU = bu[c];
            #pragma unroll
            for (int i = 0; i < 4; ++i) {
                int row = rb + ty * 4 + i;
                float si = 1.f / (1.f + expf(-(accI[i][j] + bI)));
                float th = tanhf(accU[i][j] + bU);
                Y[(size_t)row * Hc + c] = si * th;
            }
        }
    }
}

// ---------------------------------------------------------------------------
// Kernel 2: P = Qh @ Wg + bg     (M=BLc, K=Hc, N=Hc)
// ---------------------------------------------------------------------------
__global__ __launch_bounds__(256) void proj_kernel(
    const float* __restrict__ Xin,
    const float* __restrict__ Wg, const float* __restrict__ bg,
    float* __restrict__ P)
{
    __shared__ float Xs[64 * 17];
    __shared__ float Ws[16 * 160];

    const int tid = threadIdx.x;
    const int tx  = tid & 15;
    const int ty  = tid >> 4;
    const int rb  = blockIdx.x * 64;

    float acc[4][10];
    #pragma unroll
    for (int i = 0; i < 4; ++i)
        #pragma unroll
        for (int j = 0; j < 10; ++j) acc[i][j] = 0.f;

    for (int kk = 0; kk < Hc; kk += 16) {
        #pragma unroll
        for (int r = 0; r < 4; ++r) {
            int idx = tid + 256 * r;
            int m = idx >> 4, k = idx & 15;
            float v = (kk + k < Hc) ? Xin[(size_t)(rb + m) * Hc + kk + k] : 0.f;
            Xs[m * 17 + k] = v;
        }
        #pragma unroll
        for (int r = 0; r < 10; ++r) {
            int idx = tid + 256 * r;
            int k = idx / 160, c = idx - k * 160;
            bool ok = (c < Hc) && (kk + k < Hc);
            Ws[k * 160 + c] = ok ? Wg[(size_t)(kk + k) * Hc + c] : 0.f;
        }
        __syncthreads();

        #pragma unroll
        for (int k = 0; k < 16; ++k) {
            float xv[4];
            #pragma unroll
            for (int i = 0; i < 4; ++i) xv[i] = Xs[(ty * 4 + i) * 17 + k];
            #pragma unroll
            for (int j = 0; j < 10; ++j) {
                float w = Ws[k * 160 + tx + 16 * j];
                #pragma unroll
                for (int i = 0; i < 4; ++i) acc[i][j] += xv[i] * w;
            }
        }
        __syncthreads();
    }

    #pragma unroll
    for (int j = 0; j < 10; ++j) {
        int c = tx + 16 * j;
        if (c < Hc) {
            float bv = bg[c];
            #pragma unroll
            for (int i = 0; i < 4; ++i) {
                int row = rb + ty * 4 + i;
                P[(size_t)row * Hc + c] = acc[i][j] + bv;
            }
        }
    }
}

// ---------------------------------------------------------------------------
// Kernel 3: scores  Gt[b][a][q] = dot(Ah[b,a,:], P[b,q,:])   (K = Hc = 150)
// 128x128 tile per CTA, 256 threads, 8x8 microtile, KT=32, k-major smem.
// ---------------------------------------------------------------------------
__global__ __launch_bounds__(256) void score_kernel(
    const float* __restrict__ Ah,
    const float* __restrict__ P,
    float* __restrict__ G)
{
    __shared__ float As[32 * 132];
    __shared__ float Ps[32 * 132];

    const int tid = threadIdx.x;
    const int tx  = tid & 15;
    const int ty  = tid >> 4;
    const int b     = blockIdx.z;
    const int aBase = blockIdx.y * 128;
    const int qBase = blockIdx.x * 128;

    const float* Arow = Ah + ((size_t)b * Lc + aBase) * Hc;
    const float* Prow = P  + ((size_t)b * Lc + qBase) * Hc;

    float acc[8][8];
    #pragma unroll
    for (int i = 0; i < 8; ++i)
        #pragma unroll
        for (int j = 0; j < 8; ++j) acc[i][j] = 0.f;

    for (int kk = 0; kk < Hc; kk += 32) {
        const int k  = tid & 31;
        const int a0 = tid >> 5;   // 0..7
        const bool kok = (kk + k < Hc);
        #pragma unroll
        for (int it = 0; it < 16; ++it) {
            int a = a0 + it * 8;
            As[k * 132 + a] = kok ? Arow[(size_t)a * Hc + kk + k] : 0.f;
            Ps[k * 132 + a] = kok ? Prow[(size_t)a * Hc + kk + k] : 0.f;
        }
        __syncthreads();

        #pragma unroll 8
        for (int k2 = 0; k2 < 32; ++k2) {
            float av[8], pv[8];
            float4 t;
            t = *(const float4*)&As[k2 * 132 + ty * 8];     av[0]=t.x; av[1]=t.y; av[2]=t.z; av[3]=t.w;
            t = *(const float4*)&As[k2 * 132 + ty * 8 + 4]; av[4]=t.x; av[5]=t.y; av[6]=t.z; av[7]=t.w;
            t = *(const float4*)&Ps[k2 * 132 + tx * 8];     pv[0]=t.x; pv[1]=t.y; pv[2]=t.z; pv[3]=t.w;
            t = *(const float4*)&Ps[k2 * 132 + tx * 8 + 4]; pv[4]=t.x; pv[5]=t.y; pv[6]=t.z; pv[7]=t.w;
            #pragma unroll
            for (int i = 0; i < 8; ++i)
                #pragma unroll
                for (int j = 0; j < 8; ++j)
                    acc[i][j] += av[i] * pv[j];
        }
        __syncthreads();
    }

    #pragma unroll
    for (int i = 0; i < 8; ++i) {
        size_t row = ((size_t)b * Lc + aBase + ty * 8 + i) * Lc + qBase + tx * 8;
        float4 v0 = make_float4(acc[i][0], acc[i][1], acc[i][2], acc[i][3]);
        float4 v1 = make_float4(acc[i][4], acc[i][5], acc[i][6], acc[i][7]);
        *(float4*)&G[row]     = v0;
        *(float4*)&G[row + 4] = v1;
    }
}

// ---------------------------------------------------------------------------
// Kernel 4: row softmax over q (last dim of Gt). One CTA per (b,a) row.
// ---------------------------------------------------------------------------
__global__ __launch_bounds__(256) void softmax_kernel(float* __restrict__ G)
{
    __shared__ float red[32];
    const size_t base = (size_t)blockIdx.x * Lc;
    const int tid = threadIdx.x;

    float v[8];
    float m = -1e30f;
    #pragma unroll
    for (int r = 0; r < 8; ++r) {
        v[r] = G[base + tid + 256 * r];
        m = fmaxf(m, v[r]);
    }
    #pragma unroll
    for (int o = 16; o > 0; o >>= 1) m = fmaxf(m, __shfl_xor_sync(0xffffffffu, m, o));
    if ((tid & 31) == 0) red[tid >> 5] = m;
    __syncthreads();
    if (tid < 32) {
        float t = (tid < 8) ? red[tid] : -1e30f;
        #pragma unroll
        for (int o = 4; o > 0; o >>= 1) t = fmaxf(t, __shfl_xor_sync(0xffffffffu, t, o));
        if (tid == 0) red[0] = t;
    }
    __syncthreads();
    m = red[0];

    float s = 0.f;
    #pragma unroll
    for (int r = 0; r < 8; ++r) { v[r] = expf(v[r] - m); s += v[r]; }
    #pragma unroll
    for (int o = 16; o > 0; o >>= 1) s += __shfl_xor_sync(0xffffffffu, s, o);
    __syncthreads();
    if ((tid & 31) == 0) red[tid >> 5] = s;
    __syncthreads();
    if (tid < 32) {
        float t = (tid < 8) ? red[tid] : 0.f;
        #pragma unroll
        for (int o = 4; o > 0; o >>= 1) t += __shfl_xor_sync(0xffffffffu, t, o);
        if (tid == 0) red[0] = t;
    }
    __syncthreads();
    const float inv = 1.f / red[0];
    #pragma unroll
    for (int r = 0; r < 8; ++r) G[base + tid + 256 * r] = v[r] * inv;
}

// ---------------------------------------------------------------------------
// Kernel 5: Hm[b,a,:] = sum_q Gt[b,a,q] * Qh[b,q,:]
// Per batch: M=Lc (a), N=Hc, K=Lc (q). 64-row tiles, KT=16.
// ---------------------------------------------------------------------------
__global__ __launch_bounds__(256) void hm_kernel(
    const float* __restrict__ G,
    const float* __restrict__ Qh,
    float* __restrict__ Hm)
{
    __shared__ float Gs[64 * 17];
    __shared__ float Qs[16 * 160];

    const int tid = threadIdx.x;
    const int tx  = tid & 15;
    const int ty  = tid >> 4;
    const int b     = blockIdx.y;
    const int aBase = blockIdx.x * 64;

    const float* Gb = G  + ((size_t)b * Lc + aBase) * Lc;
    const float* Qb = Qh + (size_t)b * Lc * Hc;

    float acc[4][10];
    #pragma unroll
    for (int i = 0; i < 4; ++i)
        #pragma unroll
        for (int j = 0; j < 10; ++j) acc[i][j] = 0.f;

    for (int kk = 0; kk < Lc; kk += 16) {
        #pragma unroll
        for (int r = 0; r < 4; ++r) {
            int idx = tid + 256 * r;
            int m = idx >> 4, k = idx & 15;
            Gs[m * 17 + k] = Gb[(size_t)m * Lc + kk + k];
        }
        #pragma unroll
        for (int r = 0; r < 10; ++r) {
            int idx = tid + 256 * r;
            int k = idx / 160, c = idx - k * 160;
            Qs[k * 160 + c] = (c < Hc) ? Qb[(size_t)(kk + k) * Hc + c] : 0.f;
        }
        __syncthreads();

        #pragma unroll
        for (int k = 0; k < 16; ++k) {
            float gv[4];
            #pragma unroll
            for (int i = 0; i < 4; ++i) gv[i] = Gs[(ty * 4 + i) * 17 + k];
            #pragma unroll
            for (int j = 0; j < 10; ++j) {
                float w = Qs[k * 160 + tx + 16 * j];
                #pragma unroll
                for (int i = 0; i < 4; ++i) acc[i][j] += gv[i] * w;
            }
        }
        __syncthreads();
    }

    #pragma unroll
    for (int j = 0; j < 10; ++j) {
        int c = tx + 16 * j;
        if (c < Hc) {
            #pragma unroll
            for (int i = 0; i < 4; ++i)
                Hm[((size_t)b * Lc + aBase + ty * 4 + i) * Hc + c] = acc[i][j];
        }
    }
}

// ---------------------------------------------------------------------------
// Kernel 6: T = relu(Ah @ Wt[0:H] + Hm @ Wt[H:2H] + bt)
// ---------------------------------------------------------------------------
__global__ __launch_bounds__(256) void out_kernel(
    const float* __restrict__ Ah,
    const float* __restrict__ Hm,
    const float* __restrict__ Wt,
    const float* __restrict__ bt,
    float* __restrict__ T)
{
    __shared__ float Xs[64 * 17];
    __shared__ float Ws[16 * 160];

    const int tid = threadIdx.x;
    const int tx  = tid & 15;
    const int ty  = tid >> 4;
    const int rb  = blockIdx.x * 64;

    float acc[4][10];
    #pragma unroll
    for (int i = 0; i < 4; ++i)
        #pragma unroll
        for (int j = 0; j < 10; ++j) acc[i][j] = 0.f;

    for (int ph = 0; ph < 2; ++ph) {
        const float* X = ph ? Hm : Ah;
        const int wofs = ph ? Hc : 0;
        for (int kk = 0; kk < Hc; kk += 16) {
            #pragma unroll
            for (int r = 0; r < 4; ++r) {
                int idx = tid + 256 * r;
                int m = idx >> 4, k = idx & 15;
                float v = (kk + k < Hc) ? X[(size_t)(rb + m) * Hc + kk + k] : 0.f;
                Xs[m * 17 + k] = v;
            }
            #pragma unroll
            for (int r = 0; r < 10; ++r) {
                int idx = tid + 256 * r;
                int k = idx / 160, c = idx - k * 160;
                bool ok = (c < Hc) && (kk + k < Hc);
                Ws[k * 160 + c] = ok ? Wt[(size_t)(wofs + kk + k) * Hc + c] : 0.f;
            }
            __syncthreads();

            #pragma unroll
            for (int k = 0; k < 16; ++k) {
                float xv[4];
                #pragma unroll
                for (int i = 0; i < 4; ++i) xv[i] = Xs[(ty * 4 + i) * 17 + k];
                #pragma unroll
                for (int j = 0; j < 10; ++j) {
                    float w = Ws[k * 160 + tx + 16 * j];
                    #pragma unroll
                    for (int i = 0; i < 4; ++i) acc[i][j] += xv[i] * w;
                }
            }
            __syncthreads();
        }
    }

    #pragma unroll
    for (int j = 0; j < 10; ++j) {
        int c = tx + 16 * j;
        if (c < Hc) {
            float bv = bt[c];
            #pragma unroll
            for (int i = 0; i < 4; ++i) {
                int row = rb + ty * 4 + i;
                float v = acc[i][j] + bv;
                T[(size_t)row * Hc + c] = fmaxf(v, 0.f);
            }
        }
    }
}

// ---------------------------------------------------------------------------
// Launch
// Input order (metadata): Q, A, Wi, Wu, Wg, Wt, bi, bu, bg, bt
// ---------------------------------------------------------------------------
extern "C" void kernel_launch(void* const* d_in, const int* in_sizes, int n_in,
                              void* d_out, int out_size)
{
    const float* Q  = (const float*)d_in[0];
    const float* A  = (const float*)d_in[1];
    const float* Wi = (const float*)d_in[2];
    const float* Wu = (const float*)d_in[3];
    const float* Wg = (const float*)d_in[4];
    const float* Wt = (const float*)d_in[5];
    const float* bi = (const float*)d_in[6];
    const float* bu = (const float*)d_in[7];
    const float* bg = (const float*)d_in[8];
    const float* bt = (const float*)d_in[9];
    float* out = (float*)d_out;

    float *Qh, *Ah, *P, *G, *Hm;
    cudaGetSymbolAddress((void**)&Qh, g_Qh);
    cudaGetSymbolAddress((void**)&Ah, g_Ah);
    cudaGetSymbolAddress((void**)&P,  g_P);
    cudaGetSymbolAddress((void**)&G,  g_G);
    cudaGetSymbolAddress((void**)&Hm, g_Hm);

    // 1) gated projections for Q and A
    gate_kernel<<<BLc / 64, 256>>>(Q, Wi, Wu, bi, bu, Qh);
    gate_kernel<<<BLc / 64, 256>>>(A, Wi, Wu, bi, bu, Ah);

    // 2) P = Qh @ Wg + bg
    proj_kernel<<<BLc / 64, 256>>>(Qh, Wg, bg, P);

    // 3) scores Gt[b][a][q] = Ah . P
    dim3 sg(Lc / 128, Lc / 128, Bc);
    score_kernel<<<sg, 256>>>(Ah, P, G);

    // 4) softmax over q (rows of Gt)
    softmax_kernel<<<Bc * Lc, 256>>>(G);

    // 5) Hm = softmax(Gt) @ Qh
    dim3 hg(Lc / 64, Bc);
    hm_kernel<<<hg, 256>>>(G, Qh, Hm);

    // 6) T = relu([Ah, Hm] @ Wt + bt)
    out_kernel<<<BLc / 64, 256>>>(Ah, Hm, Wt, bt, out);
}

// round 8
// speedup vs baseline: 1.4458x; 1.4458x over previous
#include <cuda_runtime.h>
#include <math.h>
#include <cstdint>

#define Bc   8
#define Lc   2048
#define Dc   300
#define Hc   150
#define HP   160
#define BLc  (Bc * Lc)

__device__ float g_Qh [BLc * HP];
__device__ float g_Ah [BLc * HP];
__device__ float g_P  [BLc * HP];
__device__ float g_QhT[(size_t)Bc * HP * Lc];
__device__ float g_Hm [BLc * HP];
__device__ float g_G  [(size_t)Bc * Lc * Lc];

// ---------------- helpers (all plain sm_80+ PTX, valid on compute_103) -----
__device__ __forceinline__ uint32_t su32(const void* p) {
    return (uint32_t)__cvta_generic_to_shared(p);
}
__device__ __forceinline__ uint32_t f2tf32(float v) {
    uint32_t u; asm("cvt.rna.tf32.f32 %0, %1;" : "=r"(u) : "f"(v)); return u;
}
__device__ __forceinline__ void split32(float v, uint32_t& hi, uint32_t& lo) {
    hi = f2tf32(v);
    lo = f2tf32(v - __uint_as_float(hi));
}
__device__ __forceinline__ void mma8(float* c,
    uint32_t a0, uint32_t a1, uint32_t a2, uint32_t a3, uint32_t b0, uint32_t b1)
{
    asm volatile("mma.sync.aligned.m16n8k8.row.col.f32.tf32.tf32.f32 "
        "{%0,%1,%2,%3}, {%4,%5,%6,%7}, {%8,%9}, {%0,%1,%2,%3};"
        : "+f"(c[0]), "+f"(c[1]), "+f"(c[2]), "+f"(c[3])
        : "r"(a0), "r"(a1), "r"(a2), "r"(a3), "r"(b0), "r"(b1));
}
__device__ __forceinline__ void cpa16(uint32_t s, const void* g) {
    asm volatile("cp.async.cg.shared.global [%0], [%1], 16;" :: "r"(s), "l"(g));
}

// ---------------------------------------------------------------------------
// tf32 mma.sync GEMM: C[m][n] = sum_k A[m][k]*B[n][k]  (both K-major)
// CTA tile 128 x (NWN*32); warps 4(m) x NWN(n), warp tile 32x32.
// smem rows padded to 36 floats -> conflict-free fragment LDS.
// 3xTF32 split for ~fp32 accuracy. cp.async double buffering, KT=32.
// ---------------------------------------------------------------------------
template<int NWN>
__global__ void __launch_bounds__(128 * NWN) tf32_gemm(
    const float* __restrict__ gA, const float* __restrict__ gB, float* __restrict__ gC,
    long lda, long ldb, long ldc, long bA, long bB, long bC, int nStages)
{
    extern __shared__ float smem[];
    const int NT  = NWN * 32;
    const int ASZ = 128 * 36;
    const int BSZ = NT * 36;

    const int tid  = threadIdx.x, nthr = 128 * NWN;
    const int lane = tid & 31, wid = tid >> 5;
    const int warpM = wid & 3, warpN = wid >> 2;
    const int r4 = lane >> 2, c4 = lane & 3;

    const float* A = gA + (size_t)blockIdx.z * bA + (size_t)blockIdx.y * 128 * lda;
    const float* B = gB + (size_t)blockIdx.z * bB + (size_t)blockIdx.x * NT * ldb;
    float*       C = gC + (size_t)blockIdx.z * bC + (size_t)blockIdx.y * 128 * ldc
                        + (size_t)blockIdx.x * NT;

    float acc[2][4][4];
    #pragma unroll
    for (int mt = 0; mt < 2; ++mt)
        #pragma unroll
        for (int nt = 0; nt < 4; ++nt)
            #pragma unroll
            for (int i = 0; i < 4; ++i) acc[mt][nt][i] = 0.f;

    // stage issue: copy A[128][32], B[NT][32] (k-major, row stride 36) via cp.async
    auto issue = [&](int s) {
        const float* Ak = A + s * 32;
        const float* Bk = B + s * 32;
        float* dA = smem + (s & 1) * (ASZ + BSZ);
        float* dB = dA + ASZ;
        for (int i = tid; i < 128 * 8; i += nthr) {
            int r = i >> 3, g = i & 7;
            cpa16(su32(dA + r * 36 + g * 4), Ak + (size_t)r * lda + g * 4);
        }
        for (int i = tid; i < NT * 8; i += nthr) {
            int r = i >> 3, g = i & 7;
            cpa16(su32(dB + r * 36 + g * 4), Bk + (size_t)r * ldb + g * 4);
        }
        asm volatile("cp.async.commit_group;" ::: "memory");
    };

    issue(0);

    #pragma unroll 1
    for (int s = 0; s < nStages; ++s) {
        if (s + 1 < nStages) {
            issue(s + 1);
            asm volatile("cp.async.wait_group 1;" ::: "memory");
        } else {
            asm volatile("cp.async.wait_group 0;" ::: "memory");
        }
        __syncthreads();
        const float* cA = smem + (s & 1) * (ASZ + BSZ);
        const float* cB = cA + ASZ;

        #pragma unroll
        for (int k8 = 0; k8 < 4; ++k8) {
            const int k0 = k8 * 8;
            float aF[2][4], bF[4][2];
            #pragma unroll
            for (int mt = 0; mt < 2; ++mt) {
                int row = warpM * 32 + mt * 16 + r4;
                aF[mt][0] = cA[row * 36 + k0 + c4];
                aF[mt][1] = cA[(row + 8) * 36 + k0 + c4];
                aF[mt][2] = cA[row * 36 + k0 + c4 + 4];
                aF[mt][3] = cA[(row + 8) * 36 + k0 + c4 + 4];
            }
            #pragma unroll
            for (int nt = 0; nt < 4; ++nt) {
                int col = warpN * 32 + nt * 8 + r4;
                bF[nt][0] = cB[col * 36 + k0 + c4];
                bF[nt][1] = cB[col * 36 + k0 + c4 + 4];
            }
            #pragma unroll
            for (int mt = 0; mt < 2; ++mt) {
                uint32_t aH[4], aL[4];
                #pragma unroll
                for (int i = 0; i < 4; ++i) split32(aF[mt][i], aH[i], aL[i]);
                #pragma unroll
                for (int nt = 0; nt < 4; ++nt) {
                    uint32_t bH0, bL0, bH1, bL1;
                    split32(bF[nt][0], bH0, bL0);
                    split32(bF[nt][1], bH1, bL1);
                    mma8(acc[mt][nt], aH[0], aH[1], aH[2], aH[3], bL0, bL1);
                    mma8(acc[mt][nt], aL[0], aL[1], aL[2], aL[3], bH0, bH1);
                    mma8(acc[mt][nt], aH[0], aH[1], aH[2], aH[3], bH0, bH1);
                }
            }
        }
        __syncthreads();
    }

    #pragma unroll
    for (int mt = 0; mt < 2; ++mt) {
        int row = warpM * 32 + mt * 16 + r4;
        #pragma unroll
        for (int nt = 0; nt < 4; ++nt) {
            int col = warpN * 32 + nt * 8 + c4 * 2;
            *(float2*)(C + (size_t)row * ldc + col)       = make_float2(acc[mt][nt][0], acc[mt][nt][1]);
            *(float2*)(C + (size_t)(row + 8) * ldc + col) = make_float2(acc[mt][nt][2], acc[mt][nt][3]);
        }
    }
}

// ---------------- Kernel 1: gate (FFMA, writes HP-padded) ----------------
__global__ __launch_bounds__(256) void gate_kernel(
    const float* __restrict__ X, const float* __restrict__ Wi, const float* __restrict__ Wu,
    const float* __restrict__ bi, const float* __restrict__ bu, float* __restrict__ Y)
{
    __shared__ float Xs[64 * 17], Wis[16 * 160], Wus[16 * 160];
    const int tid = threadIdx.x, tx = tid & 15, ty = tid >> 4, rb = blockIdx.x * 64;
    float accI[4][10], accU[4][10];
    #pragma unroll
    for (int i = 0; i < 4; ++i)
        #pragma unroll
        for (int j = 0; j < 10; ++j) { accI[i][j] = 0.f; accU[i][j] = 0.f; }

    for (int kk = 0; kk < Dc; kk += 16) {
        #pragma unroll
        for (int r = 0; r < 4; ++r) {
            int idx = tid + 256 * r, m = idx >> 4, k = idx & 15;
            Xs[m * 17 + k] = (kk + k < Dc) ? X[(size_t)(rb + m) * Dc + kk + k] : 0.f;
        }
        #pragma unroll
        for (int r = 0; r < 10; ++r) {
            int idx = tid + 256 * r, k = idx / 160, c = idx - k * 160;
            bool ok = (c < Hc) && (kk + k < Dc);
            Wis[k * 160 + c] = ok ? Wi[(size_t)(kk + k) * Hc + c] : 0.f;
            Wus[k * 160 + c] = ok ? Wu[(size_t)(kk + k) * Hc + c] : 0.f;
        }
        __syncthreads();
        #pragma unroll
        for (int k = 0; k < 16; ++k) {
            float xv[4];
            #pragma unroll
            for (int i = 0; i < 4; ++i) xv[i] = Xs[(ty * 4 + i) * 17 + k];
            #pragma unroll
            for (int j = 0; j < 10; ++j) {
                float wi = Wis[k * 160 + tx + 16 * j], wu = Wus[k * 160 + tx + 16 * j];
                #pragma unroll
                for (int i = 0; i < 4; ++i) { accI[i][j] += xv[i] * wi; accU[i][j] += xv[i] * wu; }
            }
        }
        __syncthreads();
    }
    #pragma unroll
    for (int j = 0; j < 10; ++j) {
        int c = tx + 16 * j;
        float bI = (c < Hc) ? bi[c] : 0.f, bU = (c < Hc) ? bu[c] : 0.f;
        #pragma unroll
        for (int i = 0; i < 4; ++i) {
            int row = rb + ty * 4 + i;
            float v = 0.f;
            if (c < Hc) {
                float si = 1.f / (1.f + expf(-(accI[i][j] + bI)));
                v = si * tanhf(accU[i][j] + bU);
            }
            Y[(size_t)row * HP + c] = v;
        }
    }
}

// ---------------- Kernel 2: P = Qh@Wg + bg ----------------
__global__ __launch_bounds__(256) void proj_kernel(
    const float* __restrict__ Xin, const float* __restrict__ Wg,
    const float* __restrict__ bg, float* __restrict__ P)
{
    __shared__ float Xs[64 * 17], Ws[16 * 160];
    const int tid = threadIdx.x, tx = tid & 15, ty = tid >> 4, rb = blockIdx.x * 64;
    float acc[4][10];
    #pragma unroll
    for (int i = 0; i < 4; ++i)
        #pragma unroll
        for (int j = 0; j < 10; ++j) acc[i][j] = 0.f;

    for (int kk = 0; kk < Hc; kk += 16) {
        #pragma unroll
        for (int r = 0; r < 4; ++r) {
            int idx = tid + 256 * r, m = idx >> 4, k = idx & 15;
            Xs[m * 17 + k] = Xin[(size_t)(rb + m) * HP + kk + k];
        }
        #pragma unroll
        for (int r = 0; r < 10; ++r) {
            int idx = tid + 256 * r, k = idx / 160, c = idx - k * 160;
            bool ok = (c < Hc) && (kk + k < Hc);
            Ws[k * 160 + c] = ok ? Wg[(size_t)(kk + k) * Hc + c] : 0.f;
        }
        __syncthreads();
        #pragma unroll
        for (int k = 0; k < 16; ++k) {
            float xv[4];
            #pragma unroll
            for (int i = 0; i < 4; ++i) xv[i] = Xs[(ty * 4 + i) * 17 + k];
            #pragma unroll
            for (int j = 0; j < 10; ++j) {
                float w = Ws[k * 160 + tx + 16 * j];
                #pragma unroll
                for (int i = 0; i < 4; ++i) acc[i][j] += xv[i] * w;
            }
        }
        __syncthreads();
    }
    #pragma unroll
    for (int j = 0; j < 10; ++j) {
        int c = tx + 16 * j;
        float bv = (c < Hc) ? bg[c] : 0.f;
        #pragma unroll
        for (int i = 0; i < 4; ++i) {
            int row = rb + ty * 4 + i;
            P[(size_t)row * HP + c] = (c < Hc) ? (acc[i][j] + bv) : 0.f;
        }
    }
}

// ---------------- Kernel 2b: QhT[b][h][q] = Qh[b][q][h] ----------------
__global__ void transpose_kernel(const float* __restrict__ Qh, float* __restrict__ QhT)
{
    __shared__ float t[32][33];
    const int tx = threadIdx.x, ty = threadIdx.y;
    const int b = blockIdx.z, q0 = blockIdx.x * 32, h0 = blockIdx.y * 32;
    #pragma unroll
    for (int j = 0; j < 4; ++j)
        t[ty + 8 * j][tx] = Qh[((size_t)b * Lc + q0 + ty + 8 * j) * HP + h0 + tx];
    __syncthreads();
    #pragma unroll
    for (int j = 0; j < 4; ++j)
        QhT[((size_t)b * HP + h0 + ty + 8 * j) * Lc + q0 + tx] = t[tx][ty + 8 * j];
}

// ---------------- Kernel 4: row softmax over q ----------------
__global__ __launch_bounds__(256) void softmax_kernel(float* __restrict__ G)
{
    __shared__ float red[32];
    const size_t base = (size_t)blockIdx.x * Lc;
    const int tid = threadIdx.x;
    float v[8], m = -1e30f;
    #pragma unroll
    for (int r = 0; r < 8; ++r) { v[r] = G[base + tid + 256 * r]; m = fmaxf(m, v[r]); }
    #pragma unroll
    for (int o = 16; o > 0; o >>= 1) m = fmaxf(m, __shfl_xor_sync(0xffffffffu, m, o));
    if ((tid & 31) == 0) red[tid >> 5] = m;
    __syncthreads();
    if (tid < 32) {
        float t = (tid < 8) ? red[tid] : -1e30f;
        #pragma unroll
        for (int o = 4; o > 0; o >>= 1) t = fmaxf(t, __shfl_xor_sync(0xffffffffu, t, o));
        if (tid == 0) red[0] = t;
    }
    __syncthreads();
    m = red[0];
    float s = 0.f;
    #pragma unroll
    for (int r = 0; r < 8; ++r) { v[r] = expf(v[r] - m); s += v[r]; }
    #pragma unroll
    for (int o = 16; o > 0; o >>= 1) s += __shfl_xor_sync(0xffffffffu, s, o);
    __syncthreads();
    if ((tid & 31) == 0) red[tid >> 5] = s;
    __syncthreads();
    if (tid < 32) {
        float t = (tid < 8) ? red[tid] : 0.f;
        #pragma unroll
        for (int o = 4; o > 0; o >>= 1) t += __shfl_xor_sync(0xffffffffu, t, o);
        if (tid == 0) red[0] = t;
    }
    __syncthreads();
    const float inv = 1.f / red[0];
    #pragma unroll
    for (int r = 0; r < 8; ++r) G[base + tid + 256 * r] = v[r] * inv;
}

// ---------------- Kernel 6: T = relu([Ah,Hm]@Wt + bt) ----------------
__global__ __launch_bounds__(256) void out_kernel(
    const float* __restrict__ Ah, const float* __restrict__ Hm,
    const float* __restrict__ Wt, const float* __restrict__ bt, float* __restrict__ T)
{
    __shared__ float Xs[64 * 17], Ws[16 * 160];
    const int tid = threadIdx.x, tx = tid & 15, ty = tid >> 4, rb = blockIdx.x * 64;
    float acc[4][10];
    #pragma unroll
    for (int i = 0; i < 4; ++i)
        #pragma unroll
        for (int j = 0; j < 10; ++j) acc[i][j] = 0.f;

    for (int ph = 0; ph < 2; ++ph) {
        const float* X = ph ? Hm : Ah;
        const int wofs = ph ? Hc : 0;
        for (int kk = 0; kk < Hc; kk += 16) {
            #pragma unroll
            for (int r = 0; r < 4; ++r) {
                int idx = tid + 256 * r, m = idx >> 4, k = idx & 15;
                Xs[m * 17 + k] = X[(size_t)(rb + m) * HP + kk + k];
            }
            #pragma unroll
            for (int r = 0; r < 10; ++r) {
                int idx = tid + 256 * r, k = idx / 160, c = idx - k * 160;
                bool ok = (c < Hc) && (kk + k < Hc);
                Ws[k * 160 + c] = ok ? Wt[(size_t)(wofs + kk + k) * Hc + c] : 0.f;
            }
            __syncthreads();
            #pragma unroll
            for (int k = 0; k < 16; ++k) {
                float xv[4];
                #pragma unroll
                for (int i = 0; i < 4; ++i) xv[i] = Xs[(ty * 4 + i) * 17 + k];
                #pragma unroll
                for (int j = 0; j < 10; ++j) {
                    float w = Ws[k * 160 + tx + 16 * j];
                    #pragma unroll
                    for (int i = 0; i < 4; ++i) acc[i][j] += xv[i] * w;
                }
            }
            __syncthreads();
        }
    }
    #pragma unroll
    for (int j = 0; j < 10; ++j) {
        int c = tx + 16 * j;
        if (c < Hc) {
            float bv = bt[c];
            #pragma unroll
            for (int i = 0; i < 4; ++i) {
                int row = rb + ty * 4 + i;
                T[(size_t)row * Hc + c] = fmaxf(acc[i][j] + bv, 0.f);
            }
        }
    }
}

// ---------------- Launch ----------------
extern "C" void kernel_launch(void* const* d_in, const int* in_sizes, int n_in,
                              void* d_out, int out_size)
{
    const float* Q  = (const float*)d_in[0];
    const float* A  = (const float*)d_in[1];
    const float* Wi = (const float*)d_in[2];
    const float* Wu = (const float*)d_in[3];
    const float* Wg = (const float*)d_in[4];
    const float* Wt = (const float*)d_in[5];
    const float* bi = (const float*)d_in[6];
    const float* bu = (const float*)d_in[7];
    const float* bg = (const float*)d_in[8];
    const float* bt = (const float*)d_in[9];
    float* out = (float*)d_out;

    float *Qh, *Ah, *P, *QhT, *G, *Hm;
    cudaGetSymbolAddress((void**)&Qh,  g_Qh);
    cudaGetSymbolAddress((void**)&Ah,  g_Ah);
    cudaGetSymbolAddress((void**)&P,   g_P);
    cudaGetSymbolAddress((void**)&QhT, g_QhT);
    cudaGetSymbolAddress((void**)&G,   g_G);
    cudaGetSymbolAddress((void**)&Hm,  g_Hm);

    // smem: double-buffered (A:128*36 + B:NT*36) floats
    const int smem_score = 2 * (128 * 36 + 128 * 36) * 4;   // 73728 B
    const int smem_hm    = 2 * (128 * 36 + 160 * 36) * 4;   // 82944 B
    cudaFuncSetAttribute(tf32_gemm<4>, cudaFuncAttributeMaxDynamicSharedMemorySize, smem_score);
    cudaFuncSetAttribute(tf32_gemm<5>, cudaFuncAttributeMaxDynamicSharedMemorySize, smem_hm);

    gate_kernel<<<BLc / 64, 256>>>(Q, Wi, Wu, bi, bu, Qh);
    gate_kernel<<<BLc / 64, 256>>>(A, Wi, Wu, bi, bu, Ah);
    proj_kernel<<<BLc / 64, 256>>>(Qh, Wg, bg, P);

    dim3 tg(Lc / 32, HP / 32, Bc);
    transpose_kernel<<<tg, dim3(32, 8)>>>(Qh, QhT);

    // scores: C=G[b][a][q], A=Ah (m=a, k=h), B=P (n=q, k=h), K=160 -> 5 stages
    tf32_gemm<4><<<dim3(16, 16, 8), 512, smem_score>>>(
        Ah, P, G, HP, HP, Lc,
        (long)Lc * HP, (long)Lc * HP, (long)Lc * Lc, 5);

    softmax_kernel<<<Bc * Lc, 256>>>(G);

    // Hm: C=Hm[b][a][h], A=G (m=a, k=q), B=QhT (n=h, k=q), K=2048 -> 64 stages
    tf32_gemm<5><<<dim3(1, 16, 8), 640, smem_hm>>>(
        G, QhT, Hm, Lc, Lc, HP,
        (long)Lc * Lc, (long)HP * Lc, (long)Lc * HP, 64);

    out_kernel<<<BLc / 64, 256>>>(Ah, Hm, Wt, bt, out);
}